// round 4
// baseline (speedup 1.0000x reference)
#include <cuda_runtime.h>
#include <cstdint>

#define Nn 32
#define Cc 256
#define Hh 32
#define Ww 32
#define HW (Hh*Ww)
#define NCHW (Nn*Cc*Hh*Ww)
#define NPIX (Nn*Hh*Ww)
#define NCHUNK 36

// ---------------- scratch (device globals; no allocation) ----------------
__device__ uint32_t           g_xbits[NPIX*8];        // channel-packed sign bits of current conv input
__device__ uint32_t           g_wchan[2][Cc*72];      // channel-packed weights [o][j=0..8][k=0..7]
__device__ unsigned long long g_wrT[2][NCHUNK*Cc];    // r-packed weights, transposed [chunk][o]
__device__ int16_t            g_y1[NCHW];             // conv1 output (clipped int)
__device__ float              g_z[NCHW];              // conv2 output + residual
__device__ int                g_s1[Cc], g_q1[Cc];     // conv1 channel stats (exact int32)
__device__ float              g_A1[Cc], g_B1[Cc];     // bn1 sign-test coefs
__device__ double             g_S2[Cc], g_Q2[Cc];     // bn2 channel stats
__device__ float              g_A2[Cc], g_B2[Cc];
__device__ unsigned long long g_vmask[9*NCHUNK];      // per boundary-class valid-bit mask per chunk
__device__ int                g_V[9*NCHUNK];          // valid counts
__device__ float              g_regbase;              // 3*G/1024

// ---------------- init: geometric tables + stat reset + regularizer ----------------
__global__ void k_init() {
    int t = threadIdx.x;
    if (t < 9*NCHUNK) {
        int cls = t / NCHUNK, i = t % NCHUNK;
        int ht = cls / 3, wt = cls % 3;
        int r = 64*i, c = r/9, j = r - 9*c;
        unsigned long long m = 0;
        for (int b = 0; b < 64; b++) {
            int kh = j/3, kw = j - 3*kh;
            bool inval = (ht==0 && kh==0) || (ht==2 && kh==2) ||
                         (wt==0 && kw==0) || (wt==2 && kw==2);
            if (!inval) m |= 1ull << b;
            if (++j == 9) { j = 0; c++; }
        }
        g_vmask[t] = m;
        g_V[t] = __popcll(m);
    }
    if (t < Cc) { g_s1[t] = 0; g_q1[t] = 0; g_S2[t] = 0.0; g_Q2[t] = 0.0; }
    __syncthreads();
    if (t == 0) {
        // reg = r1 + 2*r2 = 3 * sum_{chunks,pixels} parity / (H*W); parity is geometric
        long long G = 0;
        int npix[3] = {1, 30, 1};
        for (int cls = 0; cls < 9; cls++) {
            long long cnt = (long long)npix[cls/3] * npix[cls%3];
            for (int i = 0; i < NCHUNK; i++)
                G += cnt * (long long)(g_V[cls*NCHUNK + i] & 1);
        }
        g_regbase = 3.0f * (float)G / (float)HW;
    }
}

// ---------------- weight packing: both layouts, both convs, one kernel ----------------
__global__ void k_packw(const float* __restrict__ w1, const float* __restrict__ w2) {
    int o    = blockIdx.x & 255;
    int slot = blockIdx.x >> 8;
    const float* w = slot ? w2 : w1;
    int warp = threadIdx.x >> 5, lane = threadIdx.x & 31;

    // r-packed transposed: bit b of word [i][o] = sign(w[o, r=64i+b])
    for (int i = warp; i < NCHUNK; i += 8) {
        unsigned lo = __ballot_sync(0xffffffffu, w[o*2304 + 64*i + lane]      >= 0.f);
        unsigned hi = __ballot_sync(0xffffffffu, w[o*2304 + 64*i + 32 + lane] >= 0.f);
        if (lane == 0)
            g_wrT[slot][i*Cc + o] = (unsigned long long)lo | ((unsigned long long)hi << 32);
    }

    // channel-packed: word [o][j][c>>5], bit (c&31)
    int c = threadIdx.x;
    float v[9];
    #pragma unroll
    for (int j = 0; j < 9; j++) v[j] = w[o*2304 + c*9 + j];
    #pragma unroll
    for (int j = 0; j < 9; j++) {
        unsigned b = __ballot_sync(0xffffffffu, v[j] >= 0.f);
        if (lane == 0) g_wchan[slot][o*72 + j*8 + (c >> 5)] = b;
    }
}

// ---------------- input packing ----------------
__global__ void k_pack_x(const float* __restrict__ x) {
    int n = blockIdx.x >> 5, h = blockIdx.x & 31;
    int w = threadIdx.x & 31, k = threadIdx.x >> 5;
    const float* base = x + ((size_t)(n*Cc + k*32) * Hh + h) * Ww + w;
    uint32_t word = 0;
    #pragma unroll 8
    for (int cc = 0; cc < 32; cc++)
        if (base[(size_t)cc * HW] >= 0.f) word |= 1u << cc;
    g_xbits[((n*Hh + h)*Ww + w)*8 + k] = word;
}

// pack sign of bn1(hardtanh preserves sign): bit = (y*A1[c] + B1[c] >= 0)
__global__ void k_pack2() {
    int n = blockIdx.x >> 5, h = blockIdx.x & 31;
    int w = threadIdx.x & 31, k = threadIdx.x >> 5;
    const int16_t* base = g_y1 + ((size_t)(n*Cc + k*32) * Hh + h) * Ww + w;
    uint32_t word = 0;
    #pragma unroll 8
    for (int cc = 0; cc < 32; cc++) {
        int c = k*32 + cc;
        float y = (float)base[(size_t)cc * HW];
        if (fmaf(y, g_A1[c], g_B1[c]) >= 0.f) word |= 1u << cc;
    }
    g_xbits[((n*Hh + h)*Ww + w)*8 + k] = word;
}

__device__ __forceinline__ int popc8(uint4 xa, uint4 xb, uint4 wa, uint4 wb) {
    return __popc(xa.x ^ wa.x) + __popc(xa.y ^ wa.y)
         + __popc(xa.z ^ wa.z) + __popc(xa.w ^ wa.w)
         + __popc(xb.x ^ wb.x) + __popc(xb.y ^ wb.y)
         + __popc(xb.z ^ wb.z) + __popc(xb.w ^ wb.w);
}

// ---------------- interior conv: 2-row strip, 8-way o-blocking, smem weights, fused stats ----------------
// quantization is an exact no-op for interior pixels (psum always even, |psum|<=64)
template<int MODE>   // 1: write y1 int16 + int stats; 2: write z = clipped + residual + float stats
__global__ void __launch_bounds__(256) k_conv_int(const float* __restrict__ x0res, int slot) {
    int n = blockIdx.x / 15, hp = blockIdx.x % 15;
    int h0 = 1 + 2*hp;                       // rows h0, h0+1; halo rows h0-1..h0+2
    __shared__ __align__(16) uint32_t sx[4][Ww][8];      // 4 KB
    __shared__ __align__(16) uint32_t sw[64*72];         // 18 KB: one 64-o stage of weights
    int t = threadIdx.x;
    ((uint4*)sx)[t] = ((const uint4*)(g_xbits + (size_t)(n*Hh + (h0-1)) * Ww * 8))[t];

    int w = t & 31, warp = t >> 5;
    int wl = (w > 0) ? w-1 : 0;
    int wr = (w < 31) ? w+1 : 31;
    const int wcol[3] = {wl, w, wr};
    bool valid = (w >= 1 && w <= 30);
    size_t base0 = (((size_t)n*Cc*Hh) + h0) * Ww + w;   // + o*HW

    for (int stage = 0; stage < 4; stage++) {
        __syncthreads();   // protect sw reuse (also covers initial sx fill)
        // cooperative load of 64 o's weights: 64*72 words = 1152 uint4
        const uint4* gsrc = (const uint4*)(g_wchan[slot] + stage*64*72);
        #pragma unroll
        for (int i = 0; i < 1152/256; i++) ((uint4*)sw)[t + i*256] = gsrc[t + i*256];
        // remainder: 1152 = 4*256 + 128
        if (t < 128) ((uint4*)sw)[1024 + t] = gsrc[1024 + t];
        __syncthreads();

        int ob = warp*8;   // this warp's 8 o's within the stage
        int s0[8], s1[8];
        #pragma unroll
        for (int oo = 0; oo < 8; oo++) { s0[oo] = 0; s1[oo] = 0; }

        #pragma unroll
        for (int j = 0; j < 9; j++) {
            int rr = j / 3;
            int wc = wcol[j % 3];
            const uint32_t* xp0 = &sx[rr][wc][0];
            uint4 xa = *(const uint4*)xp0;
            uint4 xb = *(const uint4*)(xp0 + 4);
            const uint32_t* xp1 = &sx[rr+1][wc][0];
            uint4 ya = *(const uint4*)xp1;
            uint4 yb = *(const uint4*)(xp1 + 4);
            #pragma unroll
            for (int oo = 0; oo < 8; oo++) {
                const uint4* wp = (const uint4*)(&sw[(ob + oo)*72 + j*8]);
                uint4 wa = wp[0];
                uint4 wb = wp[1];
                s0[oo] += popc8(xa, xb, wa, wb);
                s1[oo] += popc8(ya, yb, wa, wb);
            }
        }

        #pragma unroll
        for (int oo = 0; oo < 8; oo++) {
            int o = stage*64 + ob + oo;
            int a0 = min(max(2304 - 2*s0[oo], -254), 254);
            int a1 = min(max(2304 - 2*s1[oo], -254), 254);
            size_t idx = base0 + (size_t)o * HW;
            if (MODE == 1) {
                if (valid) { g_y1[idx] = (int16_t)a0; g_y1[idx + Ww] = (int16_t)a1; }
                int vs = valid ? (a0 + a1) : 0;
                int vq = valid ? (a0*a0 + a1*a1) : 0;
                vs = __reduce_add_sync(0xffffffffu, vs);
                vq = __reduce_add_sync(0xffffffffu, vq);
                if (w == 0) { atomicAdd(&g_s1[o], vs); atomicAdd(&g_q1[o], vq); }
            } else {
                float z0 = 0.f, z1 = 0.f;
                if (valid) {
                    z0 = (float)a0 + x0res[idx];
                    z1 = (float)a1 + x0res[idx + Ww];
                    g_z[idx] = z0; g_z[idx + Ww] = z1;
                }
                float fs = z0 + z1, fq = z0*z0 + z1*z1;
                #pragma unroll
                for (int d = 16; d; d >>= 1) {
                    fs += __shfl_xor_sync(0xffffffffu, fs, d);
                    fq += __shfl_xor_sync(0xffffffffu, fq, d);
                }
                if (w == 0) { atomicAdd(&g_S2[o], (double)fs); atomicAdd(&g_Q2[o], (double)fq); }
            }
        }
    }
}

// ---------------- boundary conv: exact chunked psum, banker's rounding, fused stats ----------------
template<int MODE>
__global__ void k_conv_bnd(const float* __restrict__ x0res, int slot) {
    int n = blockIdx.x / 124, b = blockIdx.x % 124;
    int h, w;
    if      (b < 32) { h = 0;      w = b; }
    else if (b < 64) { h = 31;     w = b - 32; }
    else if (b < 94) { w = 0;      h = b - 63; }
    else             { w = 31;     h = b - 93; }
    int ht  = (h == 0) ? 0 : ((h == 31) ? 2 : 1);
    int wt  = (w == 0) ? 0 : ((w == 31) ? 2 : 1);
    int cls = ht*3 + wt;

    __shared__ unsigned long long sxr[NCHUNK];
    __shared__ int soff[9];
    int t = threadIdx.x;
    int warp = t >> 5, lane = t & 31;
    if (t < 9) {
        int kh = t / 3, kw = t % 3;
        int hh = min(max(h + kh - 1, 0), 31);
        int ww = min(max(w + kw - 1, 0), 31);
        soff[t] = ((n*Hh + hh)*Ww + ww) * 8;
    }
    __syncthreads();
    // warp-parallel r-ordered word build via ballot (chunk i, bit b: r=64i+b, c=r/9, j=r%9)
    for (int i = warp; i < NCHUNK; i += 8) {
        int r0 = 64*i + lane;
        int c0 = r0 / 9, j0 = r0 - 9*c0;
        unsigned lo = __ballot_sync(0xffffffffu,
            (g_xbits[soff[j0] + (c0 >> 5)] >> (c0 & 31)) & 1u);
        int r1 = r0 + 32;
        int c1 = r1 / 9, j1 = r1 - 9*c1;
        unsigned hi = __ballot_sync(0xffffffffu,
            (g_xbits[soff[j1] + (c1 >> 5)] >> (c1 & 31)) & 1u);
        if (lane == 0)
            sxr[i] = (unsigned long long)lo | ((unsigned long long)hi << 32);
    }
    __syncthreads();

    int o = t;   // 256 threads = 256 output channels
    int acc = 0;
    #pragma unroll 4
    for (int i = 0; i < NCHUNK; i++) {
        unsigned long long X = (sxr[i] ^ g_wrT[slot][i*Cc + o]) & g_vmask[cls*NCHUNK + i];
        int psum = g_V[cls*NCHUNK + i] - 2*__popcll(X);
        int rmod = psum & 3;                   // two's-complement mod 4
        psum += (rmod == 3) - (rmod == 1);     // round-half-to-even of psum/2, *2
        acc += psum;
    }
    acc = min(max(acc, -254), 254);
    size_t idx = ((size_t)(n*Cc + o) * Hh + h) * Ww + w;
    if (MODE == 1) {
        g_y1[idx] = (int16_t)acc;
        atomicAdd(&g_s1[o], acc);
        atomicAdd(&g_q1[o], acc*acc);
    } else {
        float z = (float)acc + x0res[idx];
        g_z[idx] = z;
        atomicAdd(&g_S2[o], (double)z);
        atomicAdd(&g_Q2[o], (double)(z*z));
    }
}

// ---------------- BN coefficient kernels ----------------
__global__ void k_coef1(const float* __restrict__ gamma, const float* __restrict__ beta) {
    int o = threadIdx.x;
    double m   = (double)g_s1[o] / (double)(Nn*HW);
    double var = (double)g_q1[o] / (double)(Nn*HW) - m*m;
    float inv  = (float)(1.0 / sqrt(var + 1e-5));
    float A = gamma[o] * inv;
    g_A1[o] = A;
    g_B1[o] = beta[o] - (float)m * A;
}

__global__ void k_coef2(const float* __restrict__ gamma, const float* __restrict__ beta) {
    int o = threadIdx.x;
    double m   = g_S2[o] / (double)(Nn*HW);
    double var = g_Q2[o] / (double)(Nn*HW) - m*m;
    float inv  = (float)(1.0 / sqrt(var + 1e-5));
    float A = gamma[o] * inv;
    g_A2[o] = A;
    g_B2[o] = beta[o] - (float)m * A;
}

// ---------------- finalize: bn2 + hardtanh + regularizer scalar (float4 vectorized) ----------------
__global__ void k_final(float* __restrict__ out, const float* __restrict__ reg0, int out_size) {
    size_t v = (size_t)blockIdx.x * 256 + threadIdx.x;   // float4 index
    size_t idx = v * 4;
    if (idx < (size_t)NCHW) {
        int o = (int)((idx >> 10) & 255);
        float A = g_A2[o], B = g_B2[o];
        float4 z = *(const float4*)(g_z + idx);
        float4 r;
        r.x = fminf(fmaxf(fmaf(z.x, A, B), -1.f), 1.f);
        r.y = fminf(fmaxf(fmaf(z.y, A, B), -1.f), 1.f);
        r.z = fminf(fmaxf(fmaf(z.z, A, B), -1.f), 1.f);
        r.w = fminf(fmaxf(fmaf(z.w, A, B), -1.f), 1.f);
        *(float4*)(out + idx) = r;
    }
    if (v == 0) out[out_size - 1] = reg0[0] + g_regbase;
}

// ---------------- launch ----------------
extern "C" void kernel_launch(void* const* d_in, const int* in_sizes, int n_in,
                              void* d_out, int out_size) {
    const float* x0   = (const float*)d_in[0];
    const float* reg0 = (const float*)d_in[1];
    const float* w1   = (const float*)d_in[2];
    const float* g1   = (const float*)d_in[3];
    const float* b1   = (const float*)d_in[4];
    const float* w2   = (const float*)d_in[5];
    const float* g2   = (const float*)d_in[6];
    const float* b2   = (const float*)d_in[7];
    float* out = (float*)d_out;

    k_init<<<1, 512>>>();                       // 0
    k_packw<<<512, 256>>>(w1, w2);              // 1
    k_pack_x<<<Nn*Hh, 256>>>(x0);               // 2
    k_conv_int<1><<<Nn*15, 256>>>(nullptr, 0);  // 3
    k_conv_bnd<1><<<Nn*124, 256>>>(nullptr, 0); // 4
    k_coef1<<<1, Cc>>>(g1, b1);                 // 5
    k_pack2<<<Nn*Hh, 256>>>();                  // 6
    k_conv_int<2><<<Nn*15, 256>>>(x0, 1);       // 7
    k_conv_bnd<2><<<Nn*124, 256>>>(x0, 1);      // 8
    k_coef2<<<1, Cc>>>(g2, b2);                 // 9
    k_final<<<(NCHW/4 + 255) / 256, 256>>>(out, reg0, out_size);  // 10
}

// round 5
// speedup vs baseline: 1.0068x; 1.0068x over previous
#include <cuda_runtime.h>
#include <cstdint>

#define Nn 32
#define Cc 256
#define Hh 32
#define Ww 32
#define HW (Hh*Ww)
#define NCHW (Nn*Cc*Hh*Ww)
#define NPIX (Nn*Hh*Ww)
#define NCHUNK 36

// ---------------- scratch (device globals; no allocation) ----------------
__device__ uint32_t           g_xbits[NPIX*8];        // channel-packed sign bits of current conv input
__device__ uint32_t           g_wchan[2][Cc*72];      // channel-packed weights [o][j=0..8][k=0..7]
__device__ unsigned long long g_wrT[2][NCHUNK*Cc];    // r-packed weights, transposed [chunk][o]
__device__ int16_t            g_y1[NCHW];             // conv1 output (clipped int)
__device__ int16_t            g_y2[NCHW];             // conv2 output (clipped int, pre-residual)
__device__ int                g_s1[Cc], g_q1[Cc];     // conv1 channel stats (exact int32)
__device__ float              g_A1[Cc], g_B1[Cc];     // bn1 sign-test coefs
__device__ double             g_S2[Cc], g_Q2[Cc];     // bn2 channel stats
__device__ float              g_A2[Cc], g_B2[Cc];
__device__ unsigned long long g_vmask[9*NCHUNK];      // per boundary-class valid-bit mask per chunk
__device__ int                g_V[9*NCHUNK];          // valid counts
__device__ float              g_regbase;              // 3*G/1024

// ---------------- init: geometric tables + stat reset + regularizer ----------------
__global__ void k_init() {
    int t = threadIdx.x;
    if (t < 9*NCHUNK) {
        int cls = t / NCHUNK, i = t % NCHUNK;
        int ht = cls / 3, wt = cls % 3;
        int r = 64*i, c = r/9, j = r - 9*c;
        unsigned long long m = 0;
        for (int b = 0; b < 64; b++) {
            int kh = j/3, kw = j - 3*kh;
            bool inval = (ht==0 && kh==0) || (ht==2 && kh==2) ||
                         (wt==0 && kw==0) || (wt==2 && kw==2);
            if (!inval) m |= 1ull << b;
            if (++j == 9) { j = 0; c++; }
        }
        g_vmask[t] = m;
        g_V[t] = __popcll(m);
    }
    if (t < Cc) { g_s1[t] = 0; g_q1[t] = 0; g_S2[t] = 0.0; g_Q2[t] = 0.0; }
    __syncthreads();
    if (t == 0) {
        // reg = r1 + 2*r2 = 3 * sum_{chunks,pixels} parity / (H*W); parity is geometric
        long long G = 0;
        int npix[3] = {1, 30, 1};
        for (int cls = 0; cls < 9; cls++) {
            long long cnt = (long long)npix[cls/3] * npix[cls%3];
            for (int i = 0; i < NCHUNK; i++)
                G += cnt * (long long)(g_V[cls*NCHUNK + i] & 1);
        }
        g_regbase = 3.0f * (float)G / (float)HW;
    }
}

// ---------------- weight packing: both layouts, both convs, one kernel ----------------
__global__ void k_packw(const float* __restrict__ w1, const float* __restrict__ w2) {
    int o    = blockIdx.x & 255;
    int slot = blockIdx.x >> 8;
    const float* w = slot ? w2 : w1;
    int warp = threadIdx.x >> 5, lane = threadIdx.x & 31;

    // r-packed transposed: bit b of word [i][o] = sign(w[o, r=64i+b])
    for (int i = warp; i < NCHUNK; i += 8) {
        unsigned lo = __ballot_sync(0xffffffffu, w[o*2304 + 64*i + lane]      >= 0.f);
        unsigned hi = __ballot_sync(0xffffffffu, w[o*2304 + 64*i + 32 + lane] >= 0.f);
        if (lane == 0)
            g_wrT[slot][i*Cc + o] = (unsigned long long)lo | ((unsigned long long)hi << 32);
    }

    // channel-packed: word [o][j][c>>5], bit (c&31)
    int c = threadIdx.x;
    float v[9];
    #pragma unroll
    for (int j = 0; j < 9; j++) v[j] = w[o*2304 + c*9 + j];
    #pragma unroll
    for (int j = 0; j < 9; j++) {
        unsigned b = __ballot_sync(0xffffffffu, v[j] >= 0.f);
        if (lane == 0) g_wchan[slot][o*72 + j*8 + (c >> 5)] = b;
    }
}

// ---------------- input packing ----------------
__global__ void k_pack_x(const float* __restrict__ x) {
    int n = blockIdx.x >> 5, h = blockIdx.x & 31;
    int w = threadIdx.x & 31, k = threadIdx.x >> 5;
    const float* base = x + ((size_t)(n*Cc + k*32) * Hh + h) * Ww + w;
    uint32_t word = 0;
    #pragma unroll 8
    for (int cc = 0; cc < 32; cc++)
        if (base[(size_t)cc * HW] >= 0.f) word |= 1u << cc;
    g_xbits[((n*Hh + h)*Ww + w)*8 + k] = word;
}

// pack sign of bn1(hardtanh preserves sign): bit = (y*A1[c] + B1[c] >= 0)
__global__ void k_pack2() {
    int n = blockIdx.x >> 5, h = blockIdx.x & 31;
    int w = threadIdx.x & 31, k = threadIdx.x >> 5;
    const int16_t* base = g_y1 + ((size_t)(n*Cc + k*32) * Hh + h) * Ww + w;
    uint32_t word = 0;
    #pragma unroll 8
    for (int cc = 0; cc < 32; cc++) {
        int c = k*32 + cc;
        float y = (float)base[(size_t)cc * HW];
        if (fmaf(y, g_A1[c], g_B1[c]) >= 0.f) word |= 1u << cc;
    }
    g_xbits[((n*Hh + h)*Ww + w)*8 + k] = word;
}

__device__ __forceinline__ int popc8(uint4 xa, uint4 xb, uint4 wa, uint4 wb) {
    return __popc(xa.x ^ wa.x) + __popc(xa.y ^ wa.y)
         + __popc(xa.z ^ wa.z) + __popc(xa.w ^ wa.w)
         + __popc(xb.x ^ wb.x) + __popc(xb.y ^ wb.y)
         + __popc(xb.z ^ wb.z) + __popc(xb.w ^ wb.w);
}

// ---------------- interior conv: 2-row strip, 8-way o-blocking, packed dual accumulators ----------------
// quantization is an exact no-op for interior pixels (psum always even, |psum|<=64)
template<int MODE>   // 1: write y1 int16 + int stats; 2: write y2 int16 + float stats on z=acc+res
__global__ void __launch_bounds__(256, 3) k_conv_int(const float* __restrict__ x0res, int slot) {
    int n = blockIdx.x / 15, hp = blockIdx.x % 15;
    int h0 = 1 + 2*hp;                       // rows h0, h0+1; halo rows h0-1..h0+2
    __shared__ __align__(16) uint32_t sx[4][Ww][8];      // 4 KB
    __shared__ __align__(16) uint32_t sw[64*72];         // 18 KB: one 64-o stage of weights
    int t = threadIdx.x;
    ((uint4*)sx)[t] = ((const uint4*)(g_xbits + (size_t)(n*Hh + (h0-1)) * Ww * 8))[t];

    int w = t & 31, warp = t >> 5;
    int wl = (w > 0) ? w-1 : 0;
    int wr = (w < 31) ? w+1 : 31;
    const int wcol[3] = {wl, w, wr};
    bool valid = (w >= 1 && w <= 30);
    size_t base0 = (((size_t)n*Cc*Hh) + h0) * Ww + w;   // + o*HW

    for (int stage = 0; stage < 4; stage++) {
        __syncthreads();   // protect sw reuse (also covers initial sx fill)
        // cooperative load of 64 o's weights: 64*72 words = 1152 uint4
        const uint4* gsrc = (const uint4*)(g_wchan[slot] + stage*64*72);
        #pragma unroll
        for (int i = 0; i < 1152/256; i++) ((uint4*)sw)[t + i*256] = gsrc[t + i*256];
        if (t < 128) ((uint4*)sw)[1024 + t] = gsrc[1024 + t];
        __syncthreads();

        int ob = warp*8;   // this warp's 8 o's within the stage
        // packed accumulators: low 16 = row0 popc-sum, high 16 = row1 (each <= 2304, no carry)
        int s01[8];
        #pragma unroll
        for (int oo = 0; oo < 8; oo++) s01[oo] = 0;

        #pragma unroll
        for (int j = 0; j < 9; j++) {
            int rr = j / 3;
            int wc = wcol[j % 3];
            const uint32_t* xp0 = &sx[rr][wc][0];
            uint4 xa = *(const uint4*)xp0;
            uint4 xb = *(const uint4*)(xp0 + 4);
            const uint32_t* xp1 = &sx[rr+1][wc][0];
            uint4 ya = *(const uint4*)xp1;
            uint4 yb = *(const uint4*)(xp1 + 4);
            #pragma unroll
            for (int oo = 0; oo < 8; oo++) {
                const uint4* wp = (const uint4*)(&sw[(ob + oo)*72 + j*8]);
                uint4 wa = wp[0];
                uint4 wb = wp[1];
                int t0 = popc8(xa, xb, wa, wb);
                int t1 = popc8(ya, yb, wa, wb);
                s01[oo] += t0 + (t1 << 16);
            }
        }

        #pragma unroll
        for (int oo = 0; oo < 8; oo++) {
            int o = stage*64 + ob + oo;
            int s0 = s01[oo] & 0xFFFF;
            int s1 = s01[oo] >> 16;
            int a0 = min(max(2304 - 2*s0, -254), 254);
            int a1 = min(max(2304 - 2*s1, -254), 254);
            size_t idx = base0 + (size_t)o * HW;
            if (MODE == 1) {
                if (valid) { g_y1[idx] = (int16_t)a0; g_y1[idx + Ww] = (int16_t)a1; }
                int vs = valid ? (a0 + a1) : 0;
                int vq = valid ? (a0*a0 + a1*a1) : 0;
                vs = __reduce_add_sync(0xffffffffu, vs);
                vq = __reduce_add_sync(0xffffffffu, vq);
                if (w == 0) { atomicAdd(&g_s1[o], vs); atomicAdd(&g_q1[o], vq); }
            } else {
                float z0 = 0.f, z1 = 0.f;
                if (valid) {
                    z0 = (float)a0 + x0res[idx];
                    z1 = (float)a1 + x0res[idx + Ww];
                    g_y2[idx] = (int16_t)a0; g_y2[idx + Ww] = (int16_t)a1;
                }
                float fs = z0 + z1, fq = z0*z0 + z1*z1;
                #pragma unroll
                for (int d = 16; d; d >>= 1) {
                    fs += __shfl_xor_sync(0xffffffffu, fs, d);
                    fq += __shfl_xor_sync(0xffffffffu, fq, d);
                }
                if (w == 0) { atomicAdd(&g_S2[o], (double)fs); atomicAdd(&g_Q2[o], (double)fq); }
            }
        }
    }
}

// ---------------- boundary conv: exact chunked psum, banker's rounding, fused stats ----------------
template<int MODE>
__global__ void k_conv_bnd(const float* __restrict__ x0res, int slot) {
    int n = blockIdx.x / 124, b = blockIdx.x % 124;
    int h, w;
    if      (b < 32) { h = 0;      w = b; }
    else if (b < 64) { h = 31;     w = b - 32; }
    else if (b < 94) { w = 0;      h = b - 63; }
    else             { w = 31;     h = b - 93; }
    int ht  = (h == 0) ? 0 : ((h == 31) ? 2 : 1);
    int wt  = (w == 0) ? 0 : ((w == 31) ? 2 : 1);
    int cls = ht*3 + wt;

    __shared__ unsigned long long sxr[NCHUNK];
    __shared__ int soff[9];
    int t = threadIdx.x;
    int warp = t >> 5, lane = t & 31;
    if (t < 9) {
        int kh = t / 3, kw = t % 3;
        int hh = min(max(h + kh - 1, 0), 31);
        int ww = min(max(w + kw - 1, 0), 31);
        soff[t] = ((n*Hh + hh)*Ww + ww) * 8;
    }
    __syncthreads();
    // warp-parallel r-ordered word build via ballot (chunk i, bit b: r=64i+b, c=r/9, j=r%9)
    for (int i = warp; i < NCHUNK; i += 8) {
        int r0 = 64*i + lane;
        int c0 = r0 / 9, j0 = r0 - 9*c0;
        unsigned lo = __ballot_sync(0xffffffffu,
            (g_xbits[soff[j0] + (c0 >> 5)] >> (c0 & 31)) & 1u);
        int r1 = r0 + 32;
        int c1 = r1 / 9, j1 = r1 - 9*c1;
        unsigned hi = __ballot_sync(0xffffffffu,
            (g_xbits[soff[j1] + (c1 >> 5)] >> (c1 & 31)) & 1u);
        if (lane == 0)
            sxr[i] = (unsigned long long)lo | ((unsigned long long)hi << 32);
    }
    __syncthreads();

    int o = t;   // 256 threads = 256 output channels
    int acc = 0;
    #pragma unroll 4
    for (int i = 0; i < NCHUNK; i++) {
        unsigned long long X = (sxr[i] ^ g_wrT[slot][i*Cc + o]) & g_vmask[cls*NCHUNK + i];
        int psum = g_V[cls*NCHUNK + i] - 2*__popcll(X);
        int rmod = psum & 3;                   // two's-complement mod 4
        psum += (rmod == 3) - (rmod == 1);     // round-half-to-even of psum/2, *2
        acc += psum;
    }
    acc = min(max(acc, -254), 254);
    size_t idx = ((size_t)(n*Cc + o) * Hh + h) * Ww + w;
    if (MODE == 1) {
        g_y1[idx] = (int16_t)acc;
        atomicAdd(&g_s1[o], acc);
        atomicAdd(&g_q1[o], acc*acc);
    } else {
        float z = (float)acc + x0res[idx];
        g_y2[idx] = (int16_t)acc;
        atomicAdd(&g_S2[o], (double)z);
        atomicAdd(&g_Q2[o], (double)(z*z));
    }
}

// ---------------- BN coefficient kernels ----------------
__global__ void k_coef1(const float* __restrict__ gamma, const float* __restrict__ beta) {
    int o = threadIdx.x;
    double m   = (double)g_s1[o] / (double)(Nn*HW);
    double var = (double)g_q1[o] / (double)(Nn*HW) - m*m;
    float inv  = (float)(1.0 / sqrt(var + 1e-5));
    float A = gamma[o] * inv;
    g_A1[o] = A;
    g_B1[o] = beta[o] - (float)m * A;
}

__global__ void k_coef2(const float* __restrict__ gamma, const float* __restrict__ beta) {
    int o = threadIdx.x;
    double m   = g_S2[o] / (double)(Nn*HW);
    double var = g_Q2[o] / (double)(Nn*HW) - m*m;
    float inv  = (float)(1.0 / sqrt(var + 1e-5));
    float A = gamma[o] * inv;
    g_A2[o] = A;
    g_B2[o] = beta[o] - (float)m * A;
}

// ---------------- finalize: z = acc2 + residual, bn2 + hardtanh, regularizer scalar ----------------
__global__ void k_final(float* __restrict__ out, const float* __restrict__ reg0,
                        const float* __restrict__ x0, int out_size) {
    size_t v = (size_t)blockIdx.x * 256 + threadIdx.x;   // 4-element group index
    size_t idx = v * 4;
    if (idx < (size_t)NCHW) {
        int o = (int)((idx >> 10) & 255);
        float A = g_A2[o], B = g_B2[o];
        short4 a = *(const short4*)(g_y2 + idx);
        float4 x = *(const float4*)(x0 + idx);
        float4 r;
        // z = (float)acc + x0 — bitwise identical to the value used in fused stats
        r.x = fminf(fmaxf(fmaf((float)a.x + x.x, A, B), -1.f), 1.f);
        r.y = fminf(fmaxf(fmaf((float)a.y + x.y, A, B), -1.f), 1.f);
        r.z = fminf(fmaxf(fmaf((float)a.z + x.z, A, B), -1.f), 1.f);
        r.w = fminf(fmaxf(fmaf((float)a.w + x.w, A, B), -1.f), 1.f);
        *(float4*)(out + idx) = r;
    }
    if (v == 0) out[out_size - 1] = reg0[0] + g_regbase;
}

// ---------------- launch ----------------
extern "C" void kernel_launch(void* const* d_in, const int* in_sizes, int n_in,
                              void* d_out, int out_size) {
    const float* x0   = (const float*)d_in[0];
    const float* reg0 = (const float*)d_in[1];
    const float* w1   = (const float*)d_in[2];
    const float* g1   = (const float*)d_in[3];
    const float* b1   = (const float*)d_in[4];
    const float* w2   = (const float*)d_in[5];
    const float* g2   = (const float*)d_in[6];
    const float* b2   = (const float*)d_in[7];
    float* out = (float*)d_out;

    k_init<<<1, 512>>>();                       // 0
    k_packw<<<512, 256>>>(w1, w2);              // 1
    k_pack_x<<<Nn*Hh, 256>>>(x0);               // 2
    k_conv_int<1><<<Nn*15, 256>>>(nullptr, 0);  // 3
    k_conv_bnd<1><<<Nn*124, 256>>>(nullptr, 0); // 4
    k_coef1<<<1, Cc>>>(g1, b1);                 // 5
    k_pack2<<<Nn*Hh, 256>>>();                  // 6
    k_conv_int<2><<<Nn*15, 256>>>(x0, 1);       // 7
    k_conv_bnd<2><<<Nn*124, 256>>>(x0, 1);      // 8
    k_coef2<<<1, Cc>>>(g2, b2);                 // 9
    k_final<<<(NCHW/4 + 255) / 256, 256>>>(out, reg0, x0, out_size);  // 10
}

// round 6
// speedup vs baseline: 1.2620x; 1.2535x over previous
#include <cuda_runtime.h>
#include <cstdint>

#define Nn 32
#define Cc 256
#define Hh 32
#define Ww 32
#define HW (Hh*Ww)
#define NCHW (Nn*Cc*Hh*Ww)
#define NPIX (Nn*Hh*Ww)
#define NCHUNK 36

// ---------------- scratch (device globals; no allocation) ----------------
__device__ uint32_t           g_xbits[NPIX*8];        // channel-packed sign bits of current conv input
__device__ uint32_t           g_wchan[2][Cc*72];      // channel-packed weights [o][j=0..8][k=0..7]
__device__ unsigned long long g_wrT[2][NCHUNK*Cc];    // r-packed weights, transposed [chunk][o]
__device__ int16_t            g_y1[NCHW];             // conv1 output (clipped int)
__device__ int16_t            g_y2[NCHW];             // conv2 output (clipped int, pre-residual)
__device__ int                g_s1[Cc], g_q1[Cc];     // conv1 channel stats (exact int32)
__device__ float              g_A1[Cc], g_B1[Cc];     // bn1 sign-test coefs
__device__ double             g_S2[Cc], g_Q2[Cc];     // bn2 channel stats
__device__ float              g_A2[Cc], g_B2[Cc];
__device__ unsigned long long g_vmask[9*NCHUNK];      // per boundary-class valid-bit mask per chunk
__device__ int                g_V[9*NCHUNK];          // valid counts
__device__ float              g_regbase;              // 3*G/1024

// ---------------- init: geometric tables + stat reset + regularizer ----------------
__global__ void k_init() {
    int t = threadIdx.x;
    if (t < 9*NCHUNK) {
        int cls = t / NCHUNK, i = t % NCHUNK;
        int ht = cls / 3, wt = cls % 3;
        int r = 64*i, c = r/9, j = r - 9*c;
        unsigned long long m = 0;
        for (int b = 0; b < 64; b++) {
            int kh = j/3, kw = j - 3*kh;
            bool inval = (ht==0 && kh==0) || (ht==2 && kh==2) ||
                         (wt==0 && kw==0) || (wt==2 && kw==2);
            if (!inval) m |= 1ull << b;
            if (++j == 9) { j = 0; c++; }
        }
        g_vmask[t] = m;
        g_V[t] = __popcll(m);
    }
    if (t < Cc) { g_s1[t] = 0; g_q1[t] = 0; g_S2[t] = 0.0; g_Q2[t] = 0.0; }
    __syncthreads();
    if (t == 0) {
        // reg = r1 + 2*r2 = 3 * sum_{chunks,pixels} parity / (H*W); parity is geometric
        long long G = 0;
        int npix[3] = {1, 30, 1};
        for (int cls = 0; cls < 9; cls++) {
            long long cnt = (long long)npix[cls/3] * npix[cls%3];
            for (int i = 0; i < NCHUNK; i++)
                G += cnt * (long long)(g_V[cls*NCHUNK + i] & 1);
        }
        g_regbase = 3.0f * (float)G / (float)HW;
    }
}

// ---------------- weight packing: both layouts, both convs, one kernel ----------------
__global__ void k_packw(const float* __restrict__ w1, const float* __restrict__ w2) {
    int o    = blockIdx.x & 255;
    int slot = blockIdx.x >> 8;
    const float* w = slot ? w2 : w1;
    int warp = threadIdx.x >> 5, lane = threadIdx.x & 31;

    // r-packed transposed: bit b of word [i][o] = sign(w[o, r=64i+b])
    for (int i = warp; i < NCHUNK; i += 8) {
        unsigned lo = __ballot_sync(0xffffffffu, w[o*2304 + 64*i + lane]      >= 0.f);
        unsigned hi = __ballot_sync(0xffffffffu, w[o*2304 + 64*i + 32 + lane] >= 0.f);
        if (lane == 0)
            g_wrT[slot][i*Cc + o] = (unsigned long long)lo | ((unsigned long long)hi << 32);
    }

    // channel-packed: word [o][j][c>>5], bit (c&31)
    int c = threadIdx.x;
    float v[9];
    #pragma unroll
    for (int j = 0; j < 9; j++) v[j] = w[o*2304 + c*9 + j];
    #pragma unroll
    for (int j = 0; j < 9; j++) {
        unsigned b = __ballot_sync(0xffffffffu, v[j] >= 0.f);
        if (lane == 0) g_wchan[slot][o*72 + j*8 + (c >> 5)] = b;
    }
}

// ---------------- input packing ----------------
__global__ void k_pack_x(const float* __restrict__ x) {
    int n = blockIdx.x >> 5, h = blockIdx.x & 31;
    int w = threadIdx.x & 31, k = threadIdx.x >> 5;
    const float* base = x + ((size_t)(n*Cc + k*32) * Hh + h) * Ww + w;
    uint32_t word = 0;
    #pragma unroll 8
    for (int cc = 0; cc < 32; cc++)
        if (base[(size_t)cc * HW] >= 0.f) word |= 1u << cc;
    g_xbits[((n*Hh + h)*Ww + w)*8 + k] = word;
}

// pack sign of bn1(hardtanh preserves sign): bit = (y*A1[c] + B1[c] >= 0)
__global__ void k_pack2() {
    int n = blockIdx.x >> 5, h = blockIdx.x & 31;
    int w = threadIdx.x & 31, k = threadIdx.x >> 5;
    const int16_t* base = g_y1 + ((size_t)(n*Cc + k*32) * Hh + h) * Ww + w;
    uint32_t word = 0;
    #pragma unroll 8
    for (int cc = 0; cc < 32; cc++) {
        int c = k*32 + cc;
        float y = (float)base[(size_t)cc * HW];
        if (fmaf(y, g_A1[c], g_B1[c]) >= 0.f) word |= 1u << cc;
    }
    g_xbits[((n*Hh + h)*Ww + w)*8 + k] = word;
}

// ---------------- CSA helpers: single-LOP3 xor3 / majority ----------------
__device__ __forceinline__ uint32_t lop3_x3(uint32_t a, uint32_t b, uint32_t c) {
    uint32_t r;
    asm("lop3.b32 %0, %1, %2, %3, 0x96;" : "=r"(r) : "r"(a), "r"(b), "r"(c));
    return r;   // a ^ b ^ c
}
__device__ __forceinline__ uint32_t lop3_maj(uint32_t a, uint32_t b, uint32_t c) {
    uint32_t r;
    asm("lop3.b32 %0, %1, %2, %3, 0xE8;" : "=r"(r) : "r"(a), "r"(b), "r"(c));
    return r;   // majority(a,b,c)
}

// popcount of 8 XNOR-diff words via 4 full-adders: 4 POPC instead of 8.
// Sum popc(v0..v7) = popc(s3) + popc(v7) + 2*popc(s4) + 4*popc(c4)   (exact)
__device__ __forceinline__ int tap_count(uint4 xa, uint4 xb, uint4 wa, uint4 wb) {
    uint32_t v0 = xa.x ^ wa.x, v1 = xa.y ^ wa.y, v2 = xa.z ^ wa.z, v3 = xa.w ^ wa.w;
    uint32_t v4 = xb.x ^ wb.x, v5 = xb.y ^ wb.y, v6 = xb.z ^ wb.z, v7 = xb.w ^ wb.w;
    uint32_t sA = lop3_x3(v0, v1, v2), cA = lop3_maj(v0, v1, v2);
    uint32_t sB = lop3_x3(v3, v4, v5), cB = lop3_maj(v3, v4, v5);
    uint32_t s3 = lop3_x3(sA, sB, v6), c3 = lop3_maj(sA, sB, v6);
    uint32_t s4 = lop3_x3(cA, cB, c3), c4 = lop3_maj(cA, cB, c3);
    return __popc(s3) + __popc(v7) + 2*__popc(s4) + 4*__popc(c4);
}

// ---------------- interior conv: 2-row strip, 8-way o-blocking, CSA popcount ----------------
// quantization is an exact no-op for interior pixels (psum always even, |psum|<=64)
template<int MODE>   // 1: write y1 int16 + int stats; 2: write y2 int16 + float stats on z=acc+res
__global__ void __launch_bounds__(256, 3) k_conv_int(const float* __restrict__ x0res, int slot) {
    int n = blockIdx.x / 15, hp = blockIdx.x % 15;
    int h0 = 1 + 2*hp;                       // rows h0, h0+1; halo rows h0-1..h0+2
    __shared__ __align__(16) uint32_t sx[4][Ww][8];      // 4 KB
    __shared__ __align__(16) uint32_t sw[64*72];         // 18 KB: one 64-o stage of weights
    int t = threadIdx.x;
    ((uint4*)sx)[t] = ((const uint4*)(g_xbits + (size_t)(n*Hh + (h0-1)) * Ww * 8))[t];

    int w = t & 31, warp = t >> 5;
    int wl = (w > 0) ? w-1 : 0;
    int wr = (w < 31) ? w+1 : 31;
    const int wcol[3] = {wl, w, wr};
    bool valid = (w >= 1 && w <= 30);
    size_t base0 = (((size_t)n*Cc*Hh) + h0) * Ww + w;   // + o*HW

    for (int stage = 0; stage < 4; stage++) {
        __syncthreads();   // protect sw reuse (also covers initial sx fill)
        // cooperative load of 64 o's weights: 64*72 words = 1152 uint4
        const uint4* gsrc = (const uint4*)(g_wchan[slot] + stage*64*72);
        #pragma unroll
        for (int i = 0; i < 1152/256; i++) ((uint4*)sw)[t + i*256] = gsrc[t + i*256];
        if (t < 128) ((uint4*)sw)[1024 + t] = gsrc[1024 + t];
        __syncthreads();

        int ob = warp*8;   // this warp's 8 o's within the stage
        // packed accumulators: low 16 = row0 popc-sum, high 16 = row1 (each <= 2304, no carry)
        int s01[8];
        #pragma unroll
        for (int oo = 0; oo < 8; oo++) s01[oo] = 0;

        #pragma unroll
        for (int j = 0; j < 9; j++) {
            int rr = j / 3;
            int wc = wcol[j % 3];
            const uint32_t* xp0 = &sx[rr][wc][0];
            uint4 xa = *(const uint4*)xp0;
            uint4 xb = *(const uint4*)(xp0 + 4);
            const uint32_t* xp1 = &sx[rr+1][wc][0];
            uint4 ya = *(const uint4*)xp1;
            uint4 yb = *(const uint4*)(xp1 + 4);
            #pragma unroll
            for (int oo = 0; oo < 8; oo++) {
                const uint4* wp = (const uint4*)(&sw[(ob + oo)*72 + j*8]);
                uint4 wa = wp[0];
                uint4 wb = wp[1];
                int t0 = tap_count(xa, xb, wa, wb);
                int t1 = tap_count(ya, yb, wa, wb);
                s01[oo] += t0 + (t1 << 16);
            }
        }

        #pragma unroll
        for (int oo = 0; oo < 8; oo++) {
            int o = stage*64 + ob + oo;
            int s0 = s01[oo] & 0xFFFF;
            int s1 = s01[oo] >> 16;
            int a0 = min(max(2304 - 2*s0, -254), 254);
            int a1 = min(max(2304 - 2*s1, -254), 254);
            size_t idx = base0 + (size_t)o * HW;
            if (MODE == 1) {
                if (valid) { g_y1[idx] = (int16_t)a0; g_y1[idx + Ww] = (int16_t)a1; }
                int vs = valid ? (a0 + a1) : 0;
                int vq = valid ? (a0*a0 + a1*a1) : 0;
                vs = __reduce_add_sync(0xffffffffu, vs);
                vq = __reduce_add_sync(0xffffffffu, vq);
                if (w == 0) { atomicAdd(&g_s1[o], vs); atomicAdd(&g_q1[o], vq); }
            } else {
                float z0 = 0.f, z1 = 0.f;
                if (valid) {
                    z0 = (float)a0 + x0res[idx];
                    z1 = (float)a1 + x0res[idx + Ww];
                    g_y2[idx] = (int16_t)a0; g_y2[idx + Ww] = (int16_t)a1;
                }
                float fs = z0 + z1, fq = z0*z0 + z1*z1;
                #pragma unroll
                for (int d = 16; d; d >>= 1) {
                    fs += __shfl_xor_sync(0xffffffffu, fs, d);
                    fq += __shfl_xor_sync(0xffffffffu, fq, d);
                }
                if (w == 0) { atomicAdd(&g_S2[o], (double)fs); atomicAdd(&g_Q2[o], (double)fq); }
            }
        }
    }
}

// ---------------- boundary conv: exact chunked psum, banker's rounding, fused stats ----------------
template<int MODE>
__global__ void k_conv_bnd(const float* __restrict__ x0res, int slot) {
    int n = blockIdx.x / 124, b = blockIdx.x % 124;
    int h, w;
    if      (b < 32) { h = 0;      w = b; }
    else if (b < 64) { h = 31;     w = b - 32; }
    else if (b < 94) { w = 0;      h = b - 63; }
    else             { w = 31;     h = b - 93; }
    int ht  = (h == 0) ? 0 : ((h == 31) ? 2 : 1);
    int wt  = (w == 0) ? 0 : ((w == 31) ? 2 : 1);
    int cls = ht*3 + wt;

    __shared__ unsigned long long sxr[NCHUNK];
    __shared__ int soff[9];
    int t = threadIdx.x;
    int warp = t >> 5, lane = t & 31;
    if (t < 9) {
        int kh = t / 3, kw = t % 3;
        int hh = min(max(h + kh - 1, 0), 31);
        int ww = min(max(w + kw - 1, 0), 31);
        soff[t] = ((n*Hh + hh)*Ww + ww) * 8;
    }
    __syncthreads();
    // warp-parallel r-ordered word build via ballot (chunk i, bit b: r=64i+b, c=r/9, j=r%9)
    for (int i = warp; i < NCHUNK; i += 8) {
        int r0 = 64*i + lane;
        int c0 = r0 / 9, j0 = r0 - 9*c0;
        unsigned lo = __ballot_sync(0xffffffffu,
            (g_xbits[soff[j0] + (c0 >> 5)] >> (c0 & 31)) & 1u);
        int r1 = r0 + 32;
        int c1 = r1 / 9, j1 = r1 - 9*c1;
        unsigned hi = __ballot_sync(0xffffffffu,
            (g_xbits[soff[j1] + (c1 >> 5)] >> (c1 & 31)) & 1u);
        if (lane == 0)
            sxr[i] = (unsigned long long)lo | ((unsigned long long)hi << 32);
    }
    __syncthreads();

    int o = t;   // 256 threads = 256 output channels
    int acc = 0;
    #pragma unroll 4
    for (int i = 0; i < NCHUNK; i++) {
        unsigned long long X = (sxr[i] ^ g_wrT[slot][i*Cc + o]) & g_vmask[cls*NCHUNK + i];
        int psum = g_V[cls*NCHUNK + i] - 2*__popcll(X);
        int rmod = psum & 3;                   // two's-complement mod 4
        psum += (rmod == 3) - (rmod == 1);     // round-half-to-even of psum/2, *2
        acc += psum;
    }
    acc = min(max(acc, -254), 254);
    size_t idx = ((size_t)(n*Cc + o) * Hh + h) * Ww + w;
    if (MODE == 1) {
        g_y1[idx] = (int16_t)acc;
        atomicAdd(&g_s1[o], acc);
        atomicAdd(&g_q1[o], acc*acc);
    } else {
        float z = (float)acc + x0res[idx];
        g_y2[idx] = (int16_t)acc;
        atomicAdd(&g_S2[o], (double)z);
        atomicAdd(&g_Q2[o], (double)(z*z));
    }
}

// ---------------- BN coefficient kernels ----------------
__global__ void k_coef1(const float* __restrict__ gamma, const float* __restrict__ beta) {
    int o = threadIdx.x;
    double m   = (double)g_s1[o] / (double)(Nn*HW);
    double var = (double)g_q1[o] / (double)(Nn*HW) - m*m;
    float inv  = (float)(1.0 / sqrt(var + 1e-5));
    float A = gamma[o] * inv;
    g_A1[o] = A;
    g_B1[o] = beta[o] - (float)m * A;
}

__global__ void k_coef2(const float* __restrict__ gamma, const float* __restrict__ beta) {
    int o = threadIdx.x;
    double m   = g_S2[o] / (double)(Nn*HW);
    double var = g_Q2[o] / (double)(Nn*HW) - m*m;
    float inv  = (float)(1.0 / sqrt(var + 1e-5));
    float A = gamma[o] * inv;
    g_A2[o] = A;
    g_B2[o] = beta[o] - (float)m * A;
}

// ---------------- finalize: z = acc2 + residual, bn2 + hardtanh, regularizer scalar ----------------
__global__ void k_final(float* __restrict__ out, const float* __restrict__ reg0,
                        const float* __restrict__ x0, int out_size) {
    size_t v = (size_t)blockIdx.x * 256 + threadIdx.x;   // 4-element group index
    size_t idx = v * 4;
    if (idx < (size_t)NCHW) {
        int o = (int)((idx >> 10) & 255);
        float A = g_A2[o], B = g_B2[o];
        short4 a = *(const short4*)(g_y2 + idx);
        float4 x = *(const float4*)(x0 + idx);
        float4 r;
        // z = (float)acc + x0 — bitwise identical to the value used in fused stats
        r.x = fminf(fmaxf(fmaf((float)a.x + x.x, A, B), -1.f), 1.f);
        r.y = fminf(fmaxf(fmaf((float)a.y + x.y, A, B), -1.f), 1.f);
        r.z = fminf(fmaxf(fmaf((float)a.z + x.z, A, B), -1.f), 1.f);
        r.w = fminf(fmaxf(fmaf((float)a.w + x.w, A, B), -1.f), 1.f);
        *(float4*)(out + idx) = r;
    }
    if (v == 0) out[out_size - 1] = reg0[0] + g_regbase;
}

// ---------------- launch ----------------
extern "C" void kernel_launch(void* const* d_in, const int* in_sizes, int n_in,
                              void* d_out, int out_size) {
    const float* x0   = (const float*)d_in[0];
    const float* reg0 = (const float*)d_in[1];
    const float* w1   = (const float*)d_in[2];
    const float* g1   = (const float*)d_in[3];
    const float* b1   = (const float*)d_in[4];
    const float* w2   = (const float*)d_in[5];
    const float* g2   = (const float*)d_in[6];
    const float* b2   = (const float*)d_in[7];
    float* out = (float*)d_out;

    k_init<<<1, 512>>>();                       // 0
    k_packw<<<512, 256>>>(w1, w2);              // 1
    k_pack_x<<<Nn*Hh, 256>>>(x0);               // 2
    k_conv_int<1><<<Nn*15, 256>>>(nullptr, 0);  // 3
    k_conv_bnd<1><<<Nn*124, 256>>>(nullptr, 0); // 4
    k_coef1<<<1, Cc>>>(g1, b1);                 // 5
    k_pack2<<<Nn*Hh, 256>>>();                  // 6
    k_conv_int<2><<<Nn*15, 256>>>(x0, 1);       // 7
    k_conv_bnd<2><<<Nn*124, 256>>>(x0, 1);      // 8
    k_coef2<<<1, Cc>>>(g2, b2);                 // 9
    k_final<<<(NCHW/4 + 255) / 256, 256>>>(out, reg0, x0, out_size);  // 10
}